// round 13
// baseline (speedup 1.0000x reference)
#include <cuda_runtime.h>
#include <math.h>

#define Bdim 1024
#define Ndim 1024
#define Mdim 64
#define EPSV 1e-16f
#define COS_EPS 1e-8f

// dynamic smem layout (floats). SAVE = 7 slices x 32 rows x 16 float4 (56 KB).
#define OFF_SAVE 0
#define SAVE_F   (7 * 32 * 16 * 4)     // 14336 floats
#define OFF_SC   SAVE_F                 // 1024 scores (stored as exp(score))
#define OFF_WG   (OFF_SC + 1024)
#define OFF_W    (OFF_WG + 1024)
#define OFF_WP   (OFF_W  + 1024)
#define OFF_RA   (OFF_WP + 1024)
#define OFF_RB   (OFF_RA + 17)
#define SMEM_F   (OFF_RB + 17)
#define SMEM_BYTES (SMEM_F * 4)

// ---------------------------------------------------------------------------
__device__ __forceinline__ void cp_async8(void* smem_dst, const void* gsrc) {
    unsigned s = (unsigned)__cvta_generic_to_shared(smem_dst);
    asm volatile("cp.async.ca.shared.global [%0], [%1], 8;" :: "r"(s), "l"(gsrc));
}
#define CP_COMMIT() asm volatile("cp.async.commit_group;")
#define CP_WAIT(N)  asm volatile("cp.async.wait_group %0;" :: "n"(N))

// ---------------------------------------------------------------------------
// Block-wide SUM reduction for 512 threads, 2 barriers.
// ---------------------------------------------------------------------------
__device__ __forceinline__ float blk_sum512(float v, float* red, int tid) {
    const int lane = tid & 31, warp = tid >> 5;   // 16 warps
#pragma unroll
    for (int o = 16; o > 0; o >>= 1)
        v += __shfl_xor_sync(0xffffffffu, v, o);
    if (lane == 0) red[warp] = v;
    __syncthreads();
    if (warp == 0) {
        float t = (lane < 16) ? red[lane] : 0.f;
#pragma unroll
        for (int o = 8; o > 0; o >>= 1)
            t += __shfl_xor_sync(0xffffffffu, t, o);
        if (lane == 0) red[16] = t;
    }
    __syncthreads();
    return red[16];
}

// ---------------------------------------------------------------------------
// Fused NTM step: one block per batch b, 512 threads, 3 blocks/SM.
// Grp-0 rows j=0..6 checkpointed to smem in P1; exp folded into P1.
// ---------------------------------------------------------------------------
__global__ void __launch_bounds__(512, 3) fused_ntm(
        const float* __restrict__ mem,   const float* __restrict__ kk,
        const float* __restrict__ beta,  const float* __restrict__ gg,
        const float* __restrict__ ss,    const float* __restrict__ gamma,
        const float* __restrict__ wprev, const float* __restrict__ ee,
        const float* __restrict__ aa,    float* __restrict__ out) {
    extern __shared__ float smf[];
    float4* SAVE = (float4*)(smf + OFF_SAVE);
    float*  s_sc = smf + OFF_SC;
    float*  s_wg = smf + OFF_WG;
    float*  s_w  = smf + OFF_W;
    float*  s_wp = smf + OFF_WP;
    float*  redA = smf + OFF_RA;
    float*  redB = smf + OFF_RB;
    float4* s_r  = (float4*)(smf + OFF_SAVE);     // overlay after SAVE reads

    const int b   = blockIdx.x;
    const int tid = threadIdx.x;
    const int ml  = tid & 15;           // float4 lane within a row
    const int rg  = tid >> 4;           // row group 0..31

    const float* mb = mem + (size_t)b * Ndim * Mdim;

    // prefetch wprev row into smem
    cp_async8(&s_wp[tid * 2], wprev + b * Ndim + tid * 2);
    CP_COMMIT();

    // ---- per-b scalars ----
    const float bet = beta[b];
    const float gv  = gg[b];
    const float gm  = gamma[b];
    const float sh0 = ss[b * 3 + 0], sh1 = ss[b * 3 + 1], sh2 = ss[b * 3 + 2];

    // ---- k (+eps) and its norm ----
    float4 k4 = *(const float4*)(kk + b * Mdim + ml * 4);
    const float kx = k4.x + EPSV, ky = k4.y + EPSV;
    const float kz = k4.z + EPSV, kw = k4.w + EPSV;
    float kn = kx * kx + ky * ky + kz * kz + kw * kw;
#pragma unroll
    for (int o = 8; o > 0; o >>= 1) kn += __shfl_xor_sync(0xffffffffu, kn, o);
    const float knorm = fmaxf(sqrtf(kn), COS_EPS);

    // ---- Phase 1: scores. 4 groups x (2 halves of 4 LDG.128), butterfly
    //      reduce-scatter of 16 values; grp0 j=0..6 checkpointed to smem;
    //      stores exp(score) ----
#pragma unroll
    for (int grp = 0; grp < 4; grp++) {
        float v[16];
#pragma unroll
        for (int h = 0; h < 2; h++) {
            float4 m[4];
#pragma unroll
            for (int q = 0; q < 4; q++) {
                const int j = h * 4 + q;
                const int n = grp * 256 + j * 32 + rg;
                m[q] = *(const float4*)(mb + (size_t)n * Mdim + ml * 4);
            }
            if (grp == 0) {
#pragma unroll
                for (int q = 0; q < 4; q++) {
                    const int j = h * 4 + q;
                    if (j < 7) SAVE[(j * 32 + rg) * 16 + ml] = m[q];
                }
            }
#pragma unroll
            for (int q = 0; q < 4; q++) {
                const int j = h * 4 + q;
                float d = m[q].x * kx;
                d = fmaf(m[q].y, ky, d); d = fmaf(m[q].z, kz, d);
                d = fmaf(m[q].w, kw, d);
                float s = m[q].x * m[q].x;
                s = fmaf(m[q].y, m[q].y, s); s = fmaf(m[q].z, m[q].z, s);
                s = fmaf(m[q].w, m[q].w, s);
                v[j]     = d;
                v[8 + j] = s;
            }
        }
        int cnt = 16;
#pragma unroll
        for (int o = 8; o >= 1; o >>= 1) {
            cnt >>= 1;
            const bool hi = (ml & o);
#pragma unroll
            for (int i = 0; i < cnt; i++) {
                const float send = hi ? v[i] : v[i + cnt];
                const float recv = __shfl_xor_sync(0xffffffffu, send, o);
                v[i] = (hi ? v[i + cnt] : v[i]) + recv;
            }
        }
        const float other = __shfl_xor_sync(0xffffffffu, v[0], 8);
        if (ml < 8) {
            const int n = grp * 256 + ml * 32 + rg;
            s_sc[n] = __expf(bet * (v[0] / (fmaxf(sqrtf(other), COS_EPS) * knorm)));
        }
    }
    __syncthreads();

    // ---- Phase 2: softmax (no max; exp precomputed) / interpolate / shift /
    //      sharpen. 2 n per thread. ----
    {
        const int n0 = tid, n1 = tid + 512;
        const float ex0 = s_sc[n0];
        const float ex1 = s_sc[n1];
        const float esum = blk_sum512(ex0 + ex1, redA, tid);
        const float inv_esum = 1.f / esum;

        CP_WAIT(0);
        const float wp0 = s_wp[n0];
        const float wp1 = s_wp[n1];
        const float wg0 = fmaf(gv, ex0 * inv_esum - wp0, wp0);
        const float wg1 = fmaf(gv, ex1 * inv_esum - wp1, wp1);
        s_wg[n0] = wg0;
        s_wg[n1] = wg1;
        __syncthreads();

        const float wh0 = sh0 * s_wg[(n0 + Ndim - 1) & (Ndim - 1)]
                        + sh1 * wg0 + sh2 * s_wg[(n0 + 1) & (Ndim - 1)];
        const float wh1 = sh0 * s_wg[(n1 + Ndim - 1) & (Ndim - 1)]
                        + sh1 * wg1 + sh2 * s_wg[(n1 + 1) & (Ndim - 1)];
        const float w0 = __powf(wh0, gm);
        const float w1 = __powf(wh1, gm);
        const float wsum = blk_sum512(w0 + w1, redB, tid);
        const float inv = 1.f / (wsum + EPSV);
        s_w[n0] = w0 * inv;
        s_w[n1] = w1 * inv;
    }
    __syncthreads();

    // ---- Phase 3: read vector + erase/add write ----
    const float4 e4 = *(const float4*)(ee + b * Mdim + ml * 4);
    const float4 a4 = *(const float4*)(aa + b * Mdim + ml * 4);
    float* ob = out + (size_t)b * (Ndim + 1) * Mdim;

    float rx = 0.f, ry = 0.f, rz = 0.f, rw = 0.f;

    // grps 3..1 from gmem (reverse order, L2-hot), m[4] batches
#pragma unroll
    for (int it = 23; it >= 0; it -= 4) {
        float4 m[4];
#pragma unroll
        for (int q = 0; q < 4; q++) {
            const int n = 256 + (it - q) * 32 + rg;
            m[q] = __ldcs((const float4*)(mb + (size_t)n * Mdim + ml * 4));
        }
#pragma unroll
        for (int q = 0; q < 4; q++) {
            const int n = 256 + (it - q) * 32 + rg;
            const float wv = s_w[n];
            float4 o4;
            o4.x = fmaf(m[q].x, fmaf(-wv, e4.x, 1.f), wv * a4.x);
            o4.y = fmaf(m[q].y, fmaf(-wv, e4.y, 1.f), wv * a4.y);
            o4.z = fmaf(m[q].z, fmaf(-wv, e4.z, 1.f), wv * a4.z);
            o4.w = fmaf(m[q].w, fmaf(-wv, e4.w, 1.f), wv * a4.w);
            __stcs((float4*)(ob + (size_t)(1 + n) * Mdim + ml * 4), o4);
            rx = fmaf(wv, m[q].x, rx);
            ry = fmaf(wv, m[q].y, ry);
            rz = fmaf(wv, m[q].z, rz);
            rw = fmaf(wv, m[q].w, rw);
        }
    }
    // grp 0: j7 from gmem, j0..6 from the smem checkpoint
    {
        const int n7 = 7 * 32 + rg;
        float4 m7 = __ldcs((const float4*)(mb + (size_t)n7 * Mdim + ml * 4));
        const float wv7 = s_w[n7];
        float4 o7;
        o7.x = fmaf(m7.x, fmaf(-wv7, e4.x, 1.f), wv7 * a4.x);
        o7.y = fmaf(m7.y, fmaf(-wv7, e4.y, 1.f), wv7 * a4.y);
        o7.z = fmaf(m7.z, fmaf(-wv7, e4.z, 1.f), wv7 * a4.z);
        o7.w = fmaf(m7.w, fmaf(-wv7, e4.w, 1.f), wv7 * a4.w);
        __stcs((float4*)(ob + (size_t)(1 + n7) * Mdim + ml * 4), o7);
        rx = fmaf(wv7, m7.x, rx);
        ry = fmaf(wv7, m7.y, ry);
        rz = fmaf(wv7, m7.z, rz);
        rw = fmaf(wv7, m7.w, rw);
    }
#pragma unroll
    for (int j = 0; j < 7; j++) {
        const int n = j * 32 + rg;
        float4 m4 = SAVE[(j * 32 + rg) * 16 + ml];
        const float wv = s_w[n];
        float4 o4;
        o4.x = fmaf(m4.x, fmaf(-wv, e4.x, 1.f), wv * a4.x);
        o4.y = fmaf(m4.y, fmaf(-wv, e4.y, 1.f), wv * a4.y);
        o4.z = fmaf(m4.z, fmaf(-wv, e4.z, 1.f), wv * a4.z);
        o4.w = fmaf(m4.w, fmaf(-wv, e4.w, 1.f), wv * a4.w);
        __stcs((float4*)(ob + (size_t)(1 + n) * Mdim + ml * 4), o4);
        rx = fmaf(wv, m4.x, rx);
        ry = fmaf(wv, m4.y, ry);
        rz = fmaf(wv, m4.z, rz);
        rw = fmaf(wv, m4.w, rw);
    }

    // reduce read accumulators (512 -> 16 lanes); s_r overlays SAVE
    __syncthreads();                    // all SAVE reads complete
    s_r[tid] = make_float4(rx, ry, rz, rw);
    __syncthreads();
#pragma unroll
    for (int s = 256; s >= 16; s >>= 1) {
        if (tid < s) {
            float4 x = s_r[tid], y = s_r[tid + s];
            x.x += y.x; x.y += y.y; x.z += y.z; x.w += y.w;
            s_r[tid] = x;
        }
        __syncthreads();
    }
    if (tid < 16) __stcs((float4*)(ob + tid * 4), s_r[tid]);   // read row
}

// ---------------------------------------------------------------------------
extern "C" void kernel_launch(void* const* d_in, const int* in_sizes, int n_in,
                              void* d_out, int out_size) {
    const float* mem   = (const float*)d_in[0];
    const float* kk    = (const float*)d_in[1];
    const float* beta  = (const float*)d_in[2];
    const float* gg    = (const float*)d_in[3];
    const float* ss    = (const float*)d_in[4];
    const float* gamma = (const float*)d_in[5];
    const float* wprev = (const float*)d_in[6];
    const float* ee    = (const float*)d_in[7];
    const float* aa    = (const float*)d_in[8];
    float* out = (float*)d_out;

    cudaFuncSetAttribute(fused_ntm,
                         cudaFuncAttributeMaxDynamicSharedMemorySize, SMEM_BYTES);
    fused_ntm<<<Bdim, 512, SMEM_BYTES>>>(mem, kk, beta, gg, ss, gamma,
                                         wprev, ee, aa, out);
}

// round 14
// speedup vs baseline: 1.0392x; 1.0392x over previous
#include <cuda_runtime.h>
#include <math.h>

#define Bdim 1024
#define Ndim 1024
#define Mdim 64
#define EPSV 1e-16f
#define COS_EPS 1e-8f

// dynamic smem layout (floats). SAVE = 11 slices x 32 rows x 16 float4 (88 KB)
#define NSAVE    11
#define OFF_SAVE 0
#define SAVE_F   (NSAVE * 32 * 16 * 4)  // 22528 floats
#define OFF_SC   SAVE_F                 // 1024 floats: exp(score)
#define OFF_WG   (OFF_SC + 1024)
#define OFF_W    (OFF_WG + 1024)
#define OFF_WP   (OFF_W  + 1024)
#define OFF_RA   (OFF_WP + 1024)
#define OFF_RB   (OFF_RA + 17)
#define SMEM_F   (OFF_RB + 17 + 2)
#define SMEM_BYTES (SMEM_F * 4)

// ---------------------------------------------------------------------------
__device__ __forceinline__ void cp_async8(void* smem_dst, const void* gsrc) {
    unsigned s = (unsigned)__cvta_generic_to_shared(smem_dst);
    asm volatile("cp.async.ca.shared.global [%0], [%1], 8;" :: "r"(s), "l"(gsrc));
}
#define CP_COMMIT() asm volatile("cp.async.commit_group;")
#define CP_WAIT(N)  asm volatile("cp.async.wait_group %0;" :: "n"(N))

// ---------------------------------------------------------------------------
// Block-wide SUM reduction for 512 threads, 2 barriers.
// ---------------------------------------------------------------------------
__device__ __forceinline__ float blk_sum512(float v, float* red, int tid) {
    const int lane = tid & 31, warp = tid >> 5;   // 16 warps
#pragma unroll
    for (int o = 16; o > 0; o >>= 1)
        v += __shfl_xor_sync(0xffffffffu, v, o);
    if (lane == 0) red[warp] = v;
    __syncthreads();
    if (warp == 0) {
        float t = (lane < 16) ? red[lane] : 0.f;
#pragma unroll
        for (int o = 8; o > 0; o >>= 1)
            t += __shfl_xor_sync(0xffffffffu, t, o);
        if (lane == 0) red[16] = t;
    }
    __syncthreads();
    return red[16];
}

// ---------------------------------------------------------------------------
// Fused NTM step: one block per batch b, 512 threads, 2 blocks/SM.
// Slices 0..10 (grp0 all + grp1 j0..2) checkpointed to smem in P1.
// ---------------------------------------------------------------------------
__global__ void __launch_bounds__(512, 2) fused_ntm(
        const float* __restrict__ mem,   const float* __restrict__ kk,
        const float* __restrict__ beta,  const float* __restrict__ gg,
        const float* __restrict__ ss,    const float* __restrict__ gamma,
        const float* __restrict__ wprev, const float* __restrict__ ee,
        const float* __restrict__ aa,    float* __restrict__ out) {
    extern __shared__ float smf[];
    float4* SAVE = (float4*)(smf + OFF_SAVE);
    float*  s_sc = smf + OFF_SC;
    float*  s_wg = smf + OFF_WG;
    float*  s_w  = smf + OFF_W;
    float*  s_wp = smf + OFF_WP;
    float*  redA = smf + OFF_RA;
    float*  redB = smf + OFF_RB;
    float4* s_r  = (float4*)(smf + OFF_SAVE);   // overlay after SAVE reads

    const int b   = blockIdx.x;
    const int tid = threadIdx.x;
    const int ml  = tid & 15;           // float4 lane within a row
    const int rg  = tid >> 4;           // row group 0..31

    const float* mb = mem + (size_t)b * Ndim * Mdim;

    // prefetch wprev row into smem
    cp_async8(&s_wp[tid * 2], wprev + b * Ndim + tid * 2);
    CP_COMMIT();

    // ---- per-b scalars ----
    const float bet = beta[b];
    const float gv  = gg[b];
    const float gm  = gamma[b];
    const float sh0 = ss[b * 3 + 0], sh1 = ss[b * 3 + 1], sh2 = ss[b * 3 + 2];

    // ---- k (+eps) and its norm ----
    float4 k4 = *(const float4*)(kk + b * Mdim + ml * 4);
    const float kx = k4.x + EPSV, ky = k4.y + EPSV;
    const float kz = k4.z + EPSV, kw = k4.w + EPSV;
    float kn = kx * kx + ky * ky + kz * kz + kw * kw;
#pragma unroll
    for (int o = 8; o > 0; o >>= 1) kn += __shfl_xor_sync(0xffffffffu, kn, o);
    const float knorm = fmaxf(sqrtf(kn), COS_EPS);

    // ---- Phase 1: 4 groups x 8 front-batched LDG.128; butterfly
    //      reduce-scatter; slices 0..10 checkpointed; stores exp(score) ----
#pragma unroll
    for (int grp = 0; grp < 4; grp++) {
        float4 m[8];
#pragma unroll
        for (int j = 0; j < 8; j++) {
            const int n = grp * 256 + j * 32 + rg;
            m[j] = *(const float4*)(mb + (size_t)n * Mdim + ml * 4);
        }
        if (grp == 0) {
#pragma unroll
            for (int j = 0; j < 8; j++)
                SAVE[(j * 32 + rg) * 16 + ml] = m[j];
        } else if (grp == 1) {
#pragma unroll
            for (int j = 0; j < 3; j++)
                SAVE[((8 + j) * 32 + rg) * 16 + ml] = m[j];
        }
        float v[16];
#pragma unroll
        for (int j = 0; j < 8; j++) {
            float d = m[j].x * kx;
            d = fmaf(m[j].y, ky, d); d = fmaf(m[j].z, kz, d);
            d = fmaf(m[j].w, kw, d);
            float s = m[j].x * m[j].x;
            s = fmaf(m[j].y, m[j].y, s); s = fmaf(m[j].z, m[j].z, s);
            s = fmaf(m[j].w, m[j].w, s);
            v[j]     = d;
            v[8 + j] = s;
        }
        int cnt = 16;
#pragma unroll
        for (int o = 8; o >= 1; o >>= 1) {
            cnt >>= 1;
            const bool hi = (ml & o);
#pragma unroll
            for (int i = 0; i < cnt; i++) {
                const float send = hi ? v[i] : v[i + cnt];
                const float recv = __shfl_xor_sync(0xffffffffu, send, o);
                v[i] = (hi ? v[i + cnt] : v[i]) + recv;
            }
        }
        const float other = __shfl_xor_sync(0xffffffffu, v[0], 8);
        if (ml < 8) {
            const int n = grp * 256 + ml * 32 + rg;
            s_sc[n] = __expf(bet * (v[0] / (fmaxf(sqrtf(other), COS_EPS) * knorm)));
        }
    }
    __syncthreads();

    // ---- Phase 2: softmax (exp precomputed) / interpolate / shift /
    //      sharpen. 2 n per thread. ----
    {
        const int n0 = tid, n1 = tid + 512;
        const float ex0 = s_sc[n0];
        const float ex1 = s_sc[n1];
        const float esum = blk_sum512(ex0 + ex1, redA, tid);
        const float inv_esum = 1.f / esum;

        CP_WAIT(0);
        const float wp0 = s_wp[n0];
        const float wp1 = s_wp[n1];
        const float wg0 = fmaf(gv, ex0 * inv_esum - wp0, wp0);
        const float wg1 = fmaf(gv, ex1 * inv_esum - wp1, wp1);
        s_wg[n0] = wg0;
        s_wg[n1] = wg1;
        __syncthreads();

        const float wh0 = sh0 * s_wg[(n0 + Ndim - 1) & (Ndim - 1)]
                        + sh1 * wg0 + sh2 * s_wg[(n0 + 1) & (Ndim - 1)];
        const float wh1 = sh0 * s_wg[(n1 + Ndim - 1) & (Ndim - 1)]
                        + sh1 * wg1 + sh2 * s_wg[(n1 + 1) & (Ndim - 1)];
        const float w0 = __powf(wh0, gm);
        const float w1 = __powf(wh1, gm);
        const float wsum = blk_sum512(w0 + w1, redB, tid);
        const float inv = 1.f / (wsum + EPSV);
        s_w[n0] = w0 * inv;
        s_w[n1] = w1 * inv;
    }
    __syncthreads();

    // ---- Phase 3: read vector + erase/add write.
    //      slices 31..11 from gmem (reverse, L2-hot, 3 x m[7]);
    //      slices 10..0 from the smem checkpoint ----
    const float4 e4 = *(const float4*)(ee + b * Mdim + ml * 4);
    const float4 a4 = *(const float4*)(aa + b * Mdim + ml * 4);
    float* ob = out + (size_t)b * (Ndim + 1) * Mdim;

    float rx = 0.f, ry = 0.f, rz = 0.f, rw = 0.f;
#pragma unroll
    for (int bt = 0; bt < 3; bt++) {
        float4 m[7];
#pragma unroll
        for (int q = 0; q < 7; q++) {
            const int sidx = 31 - bt * 7 - q;            // 31..11
            const int n = sidx * 32 + rg;
            m[q] = __ldcs((const float4*)(mb + (size_t)n * Mdim + ml * 4));
        }
#pragma unroll
        for (int q = 0; q < 7; q++) {
            const int sidx = 31 - bt * 7 - q;
            const int n = sidx * 32 + rg;
            const float wv = s_w[n];
            float4 o4;
            o4.x = fmaf(m[q].x, fmaf(-wv, e4.x, 1.f), wv * a4.x);
            o4.y = fmaf(m[q].y, fmaf(-wv, e4.y, 1.f), wv * a4.y);
            o4.z = fmaf(m[q].z, fmaf(-wv, e4.z, 1.f), wv * a4.z);
            o4.w = fmaf(m[q].w, fmaf(-wv, e4.w, 1.f), wv * a4.w);
            __stcs((float4*)(ob + (size_t)(1 + n) * Mdim + ml * 4), o4);
            rx = fmaf(wv, m[q].x, rx);
            ry = fmaf(wv, m[q].y, ry);
            rz = fmaf(wv, m[q].z, rz);
            rw = fmaf(wv, m[q].w, rw);
        }
    }
    // slices 10..0 from smem
#pragma unroll
    for (int sidx = NSAVE - 1; sidx >= 0; sidx--) {
        const int n = sidx * 32 + rg;
        float4 m4 = SAVE[(sidx * 32 + rg) * 16 + ml];
        const float wv = s_w[n];
        float4 o4;
        o4.x = fmaf(m4.x, fmaf(-wv, e4.x, 1.f), wv * a4.x);
        o4.y = fmaf(m4.y, fmaf(-wv, e4.y, 1.f), wv * a4.y);
        o4.z = fmaf(m4.z, fmaf(-wv, e4.z, 1.f), wv * a4.z);
        o4.w = fmaf(m4.w, fmaf(-wv, e4.w, 1.f), wv * a4.w);
        __stcs((float4*)(ob + (size_t)(1 + n) * Mdim + ml * 4), o4);
        rx = fmaf(wv, m4.x, rx);
        ry = fmaf(wv, m4.y, ry);
        rz = fmaf(wv, m4.z, rz);
        rw = fmaf(wv, m4.w, rw);
    }

    // reduce read accumulators (512 -> 16 lanes); s_r overlays SAVE
    __syncthreads();                    // all SAVE reads complete
    s_r[tid] = make_float4(rx, ry, rz, rw);
    __syncthreads();
#pragma unroll
    for (int s = 256; s >= 16; s >>= 1) {
        if (tid < s) {
            float4 x = s_r[tid], y = s_r[tid + s];
            x.x += y.x; x.y += y.y; x.z += y.z; x.w += y.w;
            s_r[tid] = x;
        }
        __syncthreads();
    }
    if (tid < 16) __stcs((float4*)(ob + tid * 4), s_r[tid]);   // read row
}

// ---------------------------------------------------------------------------
extern "C" void kernel_launch(void* const* d_in, const int* in_sizes, int n_in,
                              void* d_out, int out_size) {
    const float* mem   = (const float*)d_in[0];
    const float* kk    = (const float*)d_in[1];
    const float* beta  = (const float*)d_in[2];
    const float* gg    = (const float*)d_in[3];
    const float* ss    = (const float*)d_in[4];
    const float* gamma = (const float*)d_in[5];
    const float* wprev = (const float*)d_in[6];
    const float* ee    = (const float*)d_in[7];
    const float* aa    = (const float*)d_in[8];
    float* out = (float*)d_out;

    cudaFuncSetAttribute(fused_ntm,
                         cudaFuncAttributeMaxDynamicSharedMemorySize, SMEM_BYTES);
    fused_ntm<<<Bdim, 512, SMEM_BYTES>>>(mem, kk, beta, gg, ss, gamma,
                                         wprev, ee, aa, out);
}

// round 15
// speedup vs baseline: 1.1791x; 1.1347x over previous
#include <cuda_runtime.h>
#include <math.h>

#define Bdim 1024
#define Ndim 1024
#define Mdim 64
#define EPSV 1e-16f
#define COS_EPS 1e-8f

// dynamic smem layout (float4 units for SAVE, floats elsewhere)
#define OFF_SAVE 0                    // 256 rows x 16 float4 = 4096 float4 (64 KB)
#define OFF_SC   (4096 * 4)           // floats: 1024 exp(score)
#define OFF_WG   (OFF_SC + 1024)      // 1024 interpolated weights
#define OFF_W    (OFF_WG + 1024)      // 1024 final weights
#define OFF_WP   (OFF_W  + 1024)      // 1024 prefetched wprev
#define OFF_RA   (OFF_WP + 1024)      // 17
#define OFF_RB   (OFF_RA + 17)        // 17
#define OFF_SR   (OFF_RB + 17 + 2)    // 512 float4 (8 KB), 16B-align pad
#define SMEM_F   (OFF_SR + 512 * 4)
#define SMEM_BYTES (SMEM_F * 4)

// ---------------------------------------------------------------------------
// cp.async helper
// ---------------------------------------------------------------------------
__device__ __forceinline__ void cp_async8(void* smem_dst, const void* gsrc) {
    unsigned s = (unsigned)__cvta_generic_to_shared(smem_dst);
    asm volatile("cp.async.ca.shared.global [%0], [%1], 8;" :: "r"(s), "l"(gsrc));
}
#define CP_COMMIT() asm volatile("cp.async.commit_group;")
#define CP_WAIT(N)  asm volatile("cp.async.wait_group %0;" :: "n"(N))

// ---------------------------------------------------------------------------
// Block-wide SUM reduction for 512 threads, 2 barriers.
// ---------------------------------------------------------------------------
__device__ __forceinline__ float blk_sum512(float v, float* red, int tid) {
    const int lane = tid & 31, warp = tid >> 5;   // 16 warps
#pragma unroll
    for (int o = 16; o > 0; o >>= 1)
        v += __shfl_xor_sync(0xffffffffu, v, o);
    if (lane == 0) red[warp] = v;
    __syncthreads();
    if (warp == 0) {
        float t = (lane < 16) ? red[lane] : 0.f;
#pragma unroll
        for (int o = 8; o > 0; o >>= 1)
            t += __shfl_xor_sync(0xffffffffu, t, o);
        if (lane == 0) red[16] = t;
    }
    __syncthreads();
    return red[16];
}

// ---------------------------------------------------------------------------
// Fused NTM step: one block per batch b, 512 threads, 2 blocks/SM.
// Grp-0 rows (longest P3 reuse distance) checkpointed to smem in P1.
// ---------------------------------------------------------------------------
__global__ void __launch_bounds__(512, 2) fused_ntm(
        const float* __restrict__ mem,   const float* __restrict__ kk,
        const float* __restrict__ beta,  const float* __restrict__ gg,
        const float* __restrict__ ss,    const float* __restrict__ gamma,
        const float* __restrict__ wprev, const float* __restrict__ ee,
        const float* __restrict__ aa,    float* __restrict__ out) {
    extern __shared__ float smf[];
    float4* SAVE = (float4*)(smf + OFF_SAVE);
    float*  s_sc = smf + OFF_SC;
    float*  s_wg = smf + OFF_WG;
    float*  s_w  = smf + OFF_W;
    float*  s_wp = smf + OFF_WP;
    float*  redA = smf + OFF_RA;
    float*  redB = smf + OFF_RB;
    float4* s_r  = (float4*)(smf + OFF_SR);

    const int b   = blockIdx.x;
    const int tid = threadIdx.x;
    const int ml  = tid & 15;           // float4 lane within a row
    const int rg  = tid >> 4;           // row group 0..31

    const float* mb = mem + (size_t)b * Ndim * Mdim;

    // prefetch wprev row into smem
    cp_async8(&s_wp[tid * 2], wprev + b * Ndim + tid * 2);
    CP_COMMIT();

    // ---- hoist per-b scalars & small vectors ----
    const float bet = beta[b];
    const float gv  = gg[b];
    const float gm  = gamma[b];
    const float sh0 = ss[b * 3 + 0], sh1 = ss[b * 3 + 1], sh2 = ss[b * 3 + 2];
    const float4 e4 = *(const float4*)(ee + b * Mdim + ml * 4);
    const float4 a4 = *(const float4*)(aa + b * Mdim + ml * 4);

    // ---- k (+eps) and its norm (reduced within each 16-lane group) ----
    float4 k4 = *(const float4*)(kk + b * Mdim + ml * 4);
    const float kx = k4.x + EPSV, ky = k4.y + EPSV;
    const float kz = k4.z + EPSV, kw = k4.w + EPSV;
    float kn = kx * kx + ky * ky + kz * kz + kw * kw;
#pragma unroll
    for (int o = 8; o > 0; o >>= 1) kn += __shfl_xor_sync(0xffffffffu, kn, o);
    const float knorm = fmaxf(sqrtf(kn), COS_EPS);

    // ---- Phase 1: scores. 4 groups x 8 front-batched LDG.128, butterfly
    //      reduce-scatter; grp 0 checkpointed to smem; stores exp(score) ----
#pragma unroll
    for (int grp = 0; grp < 4; grp++) {
        float4 m[8];
#pragma unroll
        for (int j = 0; j < 8; j++) {
            const int n = grp * 256 + j * 32 + rg;
            m[j] = *(const float4*)(mb + (size_t)n * Mdim + ml * 4);
        }
        if (grp == 0) {
#pragma unroll
            for (int j = 0; j < 8; j++)
                SAVE[(j * 32 + rg) * 16 + ml] = m[j];
        }
        float v[16];
#pragma unroll
        for (int j = 0; j < 8; j++) {
            float d = m[j].x * kx;
            d = fmaf(m[j].y, ky, d); d = fmaf(m[j].z, kz, d);
            d = fmaf(m[j].w, kw, d);
            float s = m[j].x * m[j].x;
            s = fmaf(m[j].y, m[j].y, s); s = fmaf(m[j].z, m[j].z, s);
            s = fmaf(m[j].w, m[j].w, s);
            v[j]     = d;      // lane j      gets dot of row j
            v[8 + j] = s;      // lane 8 + j  gets ssq of row j
        }
        int cnt = 16;
#pragma unroll
        for (int o = 8; o >= 1; o >>= 1) {
            cnt >>= 1;
            const bool hi = (ml & o);
#pragma unroll
            for (int i = 0; i < cnt; i++) {
                const float send = hi ? v[i] : v[i + cnt];
                const float recv = __shfl_xor_sync(0xffffffffu, send, o);
                v[i] = (hi ? v[i + cnt] : v[i]) + recv;
            }
        }
        const float other = __shfl_xor_sync(0xffffffffu, v[0], 8);
        if (ml < 8) {
            const int n = grp * 256 + ml * 32 + rg;
            s_sc[n] = __expf(bet * (v[0] / (fmaxf(sqrtf(other), COS_EPS) * knorm)));
        }
    }
    __syncthreads();

    // ---- Phase 2: softmax (exp precomputed; no max needed, |score|<=~1) /
    //      interpolate / shift / sharpen. 2 n per thread. ----
    {
        const int n0 = tid, n1 = tid + 512;
        const float ex0 = s_sc[n0];
        const float ex1 = s_sc[n1];
        const float esum = blk_sum512(ex0 + ex1, redA, tid);
        const float inv_esum = 1.f / esum;

        CP_WAIT(0);                         // wprev prefetch complete
        const float wp0 = s_wp[n0];
        const float wp1 = s_wp[n1];
        const float wg0 = fmaf(gv, ex0 * inv_esum - wp0, wp0);
        const float wg1 = fmaf(gv, ex1 * inv_esum - wp1, wp1);
        s_wg[n0] = wg0;
        s_wg[n1] = wg1;
        __syncthreads();

        const float wh0 = sh0 * s_wg[(n0 + Ndim - 1) & (Ndim - 1)]
                        + sh1 * wg0 + sh2 * s_wg[(n0 + 1) & (Ndim - 1)];
        const float wh1 = sh0 * s_wg[(n1 + Ndim - 1) & (Ndim - 1)]
                        + sh1 * wg1 + sh2 * s_wg[(n1 + 1) & (Ndim - 1)];
        const float w0 = __powf(wh0, gm);
        const float w1 = __powf(wh1, gm);
        const float wsum = blk_sum512(w0 + w1, redB, tid);
        const float inv = 1.f / (wsum + EPSV);
        s_w[n0] = w0 * inv;
        s_w[n1] = w1 * inv;
    }
    __syncthreads();

    // ---- Phase 3: read vector + erase/add write.
    //      grps 3..1 from gmem (reverse order, L2-hot); grp 0 from smem ----
    float* ob = out + (size_t)b * (Ndim + 1) * Mdim;

    float rx = 0.f, ry = 0.f, rz = 0.f, rw = 0.f;
#pragma unroll
    for (int grp = 3; grp >= 1; grp--) {
        float4 m[8];
#pragma unroll
        for (int j = 0; j < 8; j++) {
            const int n = grp * 256 + j * 32 + rg;
            m[j] = __ldcs((const float4*)(mb + (size_t)n * Mdim + ml * 4));
        }
#pragma unroll
        for (int j = 0; j < 8; j++) {
            const int n = grp * 256 + j * 32 + rg;
            const float wv = s_w[n];
            float4 o4;
            o4.x = fmaf(m[j].x, fmaf(-wv, e4.x, 1.f), wv * a4.x);
            o4.y = fmaf(m[j].y, fmaf(-wv, e4.y, 1.f), wv * a4.y);
            o4.z = fmaf(m[j].z, fmaf(-wv, e4.z, 1.f), wv * a4.z);
            o4.w = fmaf(m[j].w, fmaf(-wv, e4.w, 1.f), wv * a4.w);
            __stcs((float4*)(ob + (size_t)(1 + n) * Mdim + ml * 4), o4);
            rx = fmaf(wv, m[j].x, rx);
            ry = fmaf(wv, m[j].y, ry);
            rz = fmaf(wv, m[j].z, rz);
            rw = fmaf(wv, m[j].w, rw);
        }
    }
    // grp 0 rows from the smem checkpoint (same thread wrote them in P1)
#pragma unroll
    for (int j = 0; j < 8; j++) {
        const int n = j * 32 + rg;
        float4 m4 = SAVE[(j * 32 + rg) * 16 + ml];
        const float wv = s_w[n];
        float4 o4;
        o4.x = fmaf(m4.x, fmaf(-wv, e4.x, 1.f), wv * a4.x);
        o4.y = fmaf(m4.y, fmaf(-wv, e4.y, 1.f), wv * a4.y);
        o4.z = fmaf(m4.z, fmaf(-wv, e4.z, 1.f), wv * a4.z);
        o4.w = fmaf(m4.w, fmaf(-wv, e4.w, 1.f), wv * a4.w);
        __stcs((float4*)(ob + (size_t)(1 + n) * Mdim + ml * 4), o4);
        rx = fmaf(wv, m4.x, rx);
        ry = fmaf(wv, m4.y, ry);
        rz = fmaf(wv, m4.z, rz);
        rw = fmaf(wv, m4.w, rw);
    }

    // reduce read accumulators (512 -> 16 lanes of ml)
    s_r[tid] = make_float4(rx, ry, rz, rw);
    __syncthreads();
#pragma unroll
    for (int s = 256; s >= 16; s >>= 1) {
        if (tid < s) {
            float4 x = s_r[tid], y = s_r[tid + s];
            x.x += y.x; x.y += y.y; x.z += y.z; x.w += y.w;
            s_r[tid] = x;
        }
        __syncthreads();
    }
    if (tid < 16) __stcs((float4*)(ob + tid * 4), s_r[tid]);   // read row
}

// ---------------------------------------------------------------------------
extern "C" void kernel_launch(void* const* d_in, const int* in_sizes, int n_in,
                              void* d_out, int out_size) {
    const float* mem   = (const float*)d_in[0];
    const float* kk    = (const float*)d_in[1];
    const float* beta  = (const float*)d_in[2];
    const float* gg    = (const float*)d_in[3];
    const float* ss    = (const float*)d_in[4];
    const float* gamma = (const float*)d_in[5];
    const float* wprev = (const float*)d_in[6];
    const float* ee    = (const float*)d_in[7];
    const float* aa    = (const float*)d_in[8];
    float* out = (float*)d_out;

    cudaFuncSetAttribute(fused_ntm,
                         cudaFuncAttributeMaxDynamicSharedMemorySize, SMEM_BYTES);
    fused_ntm<<<Bdim, 512, SMEM_BYTES>>>(mem, kk, beta, gg, ss, gamma,
                                         wprev, ee, aa, out);
}

// round 16
// speedup vs baseline: 1.1987x; 1.0166x over previous
#include <cuda_runtime.h>
#include <math.h>

#define Bdim 1024
#define Ndim 1024
#define Mdim 64
#define EPSV 1e-16f
#define COS_EPS 1e-8f

// dynamic smem layout (float4 units for SAVE, floats elsewhere)
#define OFF_SAVE 0                    // 256 rows x 16 float4 = 4096 float4 (64 KB)
#define OFF_SC   (4096 * 4)           // floats: 1024 exp(score)
#define OFF_WG   (OFF_SC + 1024)      // 1024 interpolated weights
#define OFF_W    (OFF_WG + 1024)      // 1024 final weights
#define OFF_WP   (OFF_W  + 1024)      // 1024 prefetched wprev
#define OFF_RA   (OFF_WP + 1024)      // 16 partials
#define OFF_RB   (OFF_RA + 16)        // 16 partials
#define OFF_SR   (OFF_RB + 16)        // 512 float4 (8 KB), already 16B aligned
#define SMEM_F   (OFF_SR + 512 * 4)
#define SMEM_BYTES (SMEM_F * 4)

// ---------------------------------------------------------------------------
__device__ __forceinline__ void cp_async8(void* smem_dst, const void* gsrc) {
    unsigned s = (unsigned)__cvta_generic_to_shared(smem_dst);
    asm volatile("cp.async.ca.shared.global [%0], [%1], 8;" :: "r"(s), "l"(gsrc));
}
#define CP_COMMIT() asm volatile("cp.async.commit_group;")
#define CP_WAIT(N)  asm volatile("cp.async.wait_group %0;" :: "n"(N))

// ---------------------------------------------------------------------------
// Block-wide SUM for 512 threads with ONE barrier: each warp writes its
// partial, sync, then EVERY warp redundantly reduces the 16 partials.
// ---------------------------------------------------------------------------
__device__ __forceinline__ float blk_sum512_1b(float v, float* red, int tid) {
    const int lane = tid & 31, warp = tid >> 5;   // 16 warps
#pragma unroll
    for (int o = 16; o > 0; o >>= 1)
        v += __shfl_xor_sync(0xffffffffu, v, o);
    if (lane == 0) red[warp] = v;
    __syncthreads();
    float t = red[lane & 15];                     // each lane grabs a partial
#pragma unroll
    for (int o = 8; o > 0; o >>= 1)
        t += __shfl_xor_sync(0xffffffffu, t, o);
    return t;                                     // uniform across warp
}

// ---------------------------------------------------------------------------
// Fused NTM step: one block per batch b, 512 threads, 2 blocks/SM.
// Grp-0 rows (longest P3 reuse distance) checkpointed to smem in P1.
// ---------------------------------------------------------------------------
__global__ void __launch_bounds__(512, 2) fused_ntm(
        const float* __restrict__ mem,   const float* __restrict__ kk,
        const float* __restrict__ beta,  const float* __restrict__ gg,
        const float* __restrict__ ss,    const float* __restrict__ gamma,
        const float* __restrict__ wprev, const float* __restrict__ ee,
        const float* __restrict__ aa,    float* __restrict__ out) {
    extern __shared__ float smf[];
    float4* SAVE = (float4*)(smf + OFF_SAVE);
    float*  s_sc = smf + OFF_SC;
    float*  s_wg = smf + OFF_WG;
    float*  s_w  = smf + OFF_W;
    float*  s_wp = smf + OFF_WP;
    float*  redA = smf + OFF_RA;
    float*  redB = smf + OFF_RB;
    float4* s_r  = (float4*)(smf + OFF_SR);

    const int b   = blockIdx.x;
    const int tid = threadIdx.x;
    const int ml  = tid & 15;           // float4 lane within a row
    const int rg  = tid >> 4;           // row group 0..31

    const float* mb = mem + (size_t)b * Ndim * Mdim;

    // prefetch wprev row into smem
    cp_async8(&s_wp[tid * 2], wprev + b * Ndim + tid * 2);
    CP_COMMIT();

    // ---- hoist per-b scalars & small vectors ----
    const float bet = beta[b];
    const float gv  = gg[b];
    const float gm  = gamma[b];
    const float sh0 = ss[b * 3 + 0], sh1 = ss[b * 3 + 1], sh2 = ss[b * 3 + 2];
    const float4 e4 = *(const float4*)(ee + b * Mdim + ml * 4);
    const float4 a4 = *(const float4*)(aa + b * Mdim + ml * 4);

    // ---- k (+eps) and its norm (reduced within each 16-lane group) ----
    float4 k4 = *(const float4*)(kk + b * Mdim + ml * 4);
    const float kx = k4.x + EPSV, ky = k4.y + EPSV;
    const float kz = k4.z + EPSV, kw = k4.w + EPSV;
    float kn = kx * kx + ky * ky + kz * kz + kw * kw;
#pragma unroll
    for (int o = 8; o > 0; o >>= 1) kn += __shfl_xor_sync(0xffffffffu, kn, o);
    const float knorm = fmaxf(sqrtf(kn), COS_EPS);

    // ---- Phase 1: scores. 4 groups x 8 front-batched LDG.128, butterfly
    //      reduce-scatter; grp 0 checkpointed to smem; stores exp(score) ----
#pragma unroll
    for (int grp = 0; grp < 4; grp++) {
        float4 m[8];
#pragma unroll
        for (int j = 0; j < 8; j++) {
            const int n = grp * 256 + j * 32 + rg;
            m[j] = *(const float4*)(mb + (size_t)n * Mdim + ml * 4);
        }
        if (grp == 0) {
#pragma unroll
            for (int j = 0; j < 8; j++)
                SAVE[(j * 32 + rg) * 16 + ml] = m[j];
        }
        float v[16];
#pragma unroll
        for (int j = 0; j < 8; j++) {
            float d = m[j].x * kx;
            d = fmaf(m[j].y, ky, d); d = fmaf(m[j].z, kz, d);
            d = fmaf(m[j].w, kw, d);
            float s = m[j].x * m[j].x;
            s = fmaf(m[j].y, m[j].y, s); s = fmaf(m[j].z, m[j].z, s);
            s = fmaf(m[j].w, m[j].w, s);
            v[j]     = d;      // lane j      gets dot of row j
            v[8 + j] = s;      // lane 8 + j  gets ssq of row j
        }
        int cnt = 16;
#pragma unroll
        for (int o = 8; o >= 1; o >>= 1) {
            cnt >>= 1;
            const bool hi = (ml & o);
#pragma unroll
            for (int i = 0; i < cnt; i++) {
                const float send = hi ? v[i] : v[i + cnt];
                const float recv = __shfl_xor_sync(0xffffffffu, send, o);
                v[i] = (hi ? v[i + cnt] : v[i]) + recv;
            }
        }
        const float other = __shfl_xor_sync(0xffffffffu, v[0], 8);
        if (ml < 8) {
            const int n = grp * 256 + ml * 32 + rg;
            s_sc[n] = __expf(bet * (v[0] / (fmaxf(sqrtf(other), COS_EPS) * knorm)));
        }
    }
    __syncthreads();

    // ---- Phase 2: softmax (exp precomputed) / interpolate / shift /
    //      sharpen. 2 n per thread; 1-barrier reductions; wp hoisted. ----
    {
        const int n0 = tid, n1 = tid + 512;
        const float ex0 = s_sc[n0];
        const float ex1 = s_sc[n1];
        CP_WAIT(0);                          // wprev ready; load BEFORE reduce
        const float wp0 = s_wp[n0];
        const float wp1 = s_wp[n1];

        const float esum = blk_sum512_1b(ex0 + ex1, redA, tid);
        const float inv_esum = 1.f / esum;
        const float wg0 = fmaf(gv, ex0 * inv_esum - wp0, wp0);
        const float wg1 = fmaf(gv, ex1 * inv_esum - wp1, wp1);
        s_wg[n0] = wg0;
        s_wg[n1] = wg1;
        __syncthreads();

        const float wh0 = sh0 * s_wg[(n0 + Ndim - 1) & (Ndim - 1)]
                        + sh1 * wg0 + sh2 * s_wg[(n0 + 1) & (Ndim - 1)];
        const float wh1 = sh0 * s_wg[(n1 + Ndim - 1) & (Ndim - 1)]
                        + sh1 * wg1 + sh2 * s_wg[(n1 + 1) & (Ndim - 1)];
        const float w0 = __powf(wh0, gm);
        const float w1 = __powf(wh1, gm);
        const float wsum = blk_sum512_1b(w0 + w1, redB, tid);
        const float inv = 1.f / (wsum + EPSV);
        s_w[n0] = w0 * inv;
        s_w[n1] = w1 * inv;
    }
    __syncthreads();

    // ---- Phase 3: read vector + erase/add write.
    //      grps 3..1 from gmem (reverse order, L2-hot); grp 0 from smem ----
    float* ob = out + (size_t)b * (Ndim + 1) * Mdim;

    float rx = 0.f, ry = 0.f, rz = 0.f, rw = 0.f;
#pragma unroll
    for (int grp = 3; grp >= 1; grp--) {
        float4 m[8];
#pragma unroll
        for (int j = 0; j < 8; j++) {
            const int n = grp * 256 + j * 32 + rg;
            m[j] = __ldcs((const float4*)(mb + (size_t)n * Mdim + ml * 4));
        }
#pragma unroll
        for (int j = 0; j < 8; j++) {
            const int n = grp * 256 + j * 32 + rg;
            const float wv = s_w[n];
            float4 o4;
            o4.x = fmaf(m[j].x, fmaf(-wv, e4.x, 1.f), wv * a4.x);
            o4.y = fmaf(m[j].y, fmaf(-wv, e4.y, 1.f), wv * a4.y);
            o4.z = fmaf(m[j].z, fmaf(-wv, e4.z, 1.f), wv * a4.z);
            o4.w = fmaf(m[j].w, fmaf(-wv, e4.w, 1.f), wv * a4.w);
            __stcs((float4*)(ob + (size_t)(1 + n) * Mdim + ml * 4), o4);
            rx = fmaf(wv, m[j].x, rx);
            ry = fmaf(wv, m[j].y, ry);
            rz = fmaf(wv, m[j].z, rz);
            rw = fmaf(wv, m[j].w, rw);
        }
    }
    // grp 0 rows from the smem checkpoint (same thread wrote them in P1)
#pragma unroll
    for (int j = 0; j < 8; j++) {
        const int n = j * 32 + rg;
        float4 m4 = SAVE[(j * 32 + rg) * 16 + ml];
        const float wv = s_w[n];
        float4 o4;
        o4.x = fmaf(m4.x, fmaf(-wv, e4.x, 1.f), wv * a4.x);
        o4.y = fmaf(m4.y, fmaf(-wv, e4.y, 1.f), wv * a4.y);
        o4.z = fmaf(m4.z, fmaf(-wv, e4.z, 1.f), wv * a4.z);
        o4.w = fmaf(m4.w, fmaf(-wv, e4.w, 1.f), wv * a4.w);
        __stcs((float4*)(ob + (size_t)(1 + n) * Mdim + ml * 4), o4);
        rx = fmaf(wv, m4.x, rx);
        ry = fmaf(wv, m4.y, ry);
        rz = fmaf(wv, m4.z, rz);
        rw = fmaf(wv, m4.w, rw);
    }

    // reduce read accumulators (512 -> 16 lanes of ml)
    s_r[tid] = make_float4(rx, ry, rz, rw);
    __syncthreads();
#pragma unroll
    for (int s = 256; s >= 16; s >>= 1) {
        if (tid < s) {
            float4 x = s_r[tid], y = s_r[tid + s];
            x.x += y.x; x.y += y.y; x.z += y.z; x.w += y.w;
            s_r[tid] = x;
        }
        __syncthreads();
    }
    if (tid < 16) __stcs((float4*)(ob + tid * 4), s_r[tid]);   // read row
}

// ---------------------------------------------------------------------------
extern "C" void kernel_launch(void* const* d_in, const int* in_sizes, int n_in,
                              void* d_out, int out_size) {
    const float* mem   = (const float*)d_in[0];
    const float* kk    = (const float*)d_in[1];
    const float* beta  = (const float*)d_in[2];
    const float* gg    = (const float*)d_in[3];
    const float* ss    = (const float*)d_in[4];
    const float* gamma = (const float*)d_in[5];
    const float* wprev = (const float*)d_in[6];
    const float* ee    = (const float*)d_in[7];
    const float* aa    = (const float*)d_in[8];
    float* out = (float*)d_out;

    cudaFuncSetAttribute(fused_ntm,
                         cudaFuncAttributeMaxDynamicSharedMemorySize, SMEM_BYTES);
    fused_ntm<<<Bdim, 512, SMEM_BYTES>>>(mem, kk, beta, gg, ss, gamma,
                                         wprev, ee, aa, out);
}

// round 17
// speedup vs baseline: 1.2043x; 1.0047x over previous
#include <cuda_runtime.h>
#include <math.h>

#define Bdim 1024
#define Ndim 1024
#define Mdim 64
#define EPSV 1e-16f
#define COS_EPS 1e-8f

// dynamic smem layout (floats)
#define OFF_SAVE 0                    // 256 rows x 16 float4 (64 KB)
#define OFF_SC   (4096 * 4)           // 1024: exp(score) -> reused as wg
#define OFF_W    (OFF_SC + 1024)      // 1024: final weights
#define OFF_WP   (OFF_W  + 1024)      // 1024: prefetched wprev
#define OFF_RA   (OFF_WP + 1024)      // 16 partials
#define OFF_RB   (OFF_RA + 16)        // 16 partials
#define OFF_PF   (OFF_RB + 16)        // 2 slices x 512 float4 (16 KB); s_r overlays
#define SMEM_F   (OFF_PF + 2 * 512 * 4)
#define SMEM_BYTES (SMEM_F * 4)

// ---------------------------------------------------------------------------
__device__ __forceinline__ void cp_async16(void* smem_dst, const void* gsrc) {
    unsigned s = (unsigned)__cvta_generic_to_shared(smem_dst);
    asm volatile("cp.async.cg.shared.global [%0], [%1], 16;" :: "r"(s), "l"(gsrc));
}
__device__ __forceinline__ void cp_async8(void* smem_dst, const void* gsrc) {
    unsigned s = (unsigned)__cvta_generic_to_shared(smem_dst);
    asm volatile("cp.async.ca.shared.global [%0], [%1], 8;" :: "r"(s), "l"(gsrc));
}
#define CP_COMMIT() asm volatile("cp.async.commit_group;")
#define CP_WAIT(N)  asm volatile("cp.async.wait_group %0;" :: "n"(N))

// ---------------------------------------------------------------------------
// Block-wide SUM for 512 threads with ONE barrier.
// ---------------------------------------------------------------------------
__device__ __forceinline__ float blk_sum512_1b(float v, float* red, int tid) {
    const int lane = tid & 31, warp = tid >> 5;   // 16 warps
#pragma unroll
    for (int o = 16; o > 0; o >>= 1)
        v += __shfl_xor_sync(0xffffffffu, v, o);
    if (lane == 0) red[warp] = v;
    __syncthreads();
    float t = red[lane & 15];
#pragma unroll
    for (int o = 8; o > 0; o >>= 1)
        t += __shfl_xor_sync(0xffffffffu, t, o);
    return t;
}

// ---------------------------------------------------------------------------
// Fused NTM step: one block per batch b, 512 threads, 2 blocks/SM.
// Grp-0 rows checkpointed to smem in P1; grp3 j0/j1 cp.async-bridged over P2.
// ---------------------------------------------------------------------------
__global__ void __launch_bounds__(512, 2) fused_ntm(
        const float* __restrict__ mem,   const float* __restrict__ kk,
        const float* __restrict__ beta,  const float* __restrict__ gg,
        const float* __restrict__ ss,    const float* __restrict__ gamma,
        const float* __restrict__ wprev, const float* __restrict__ ee,
        const float* __restrict__ aa,    float* __restrict__ out) {
    extern __shared__ float smf[];
    float4* SAVE = (float4*)(smf + OFF_SAVE);
    float*  s_sc = smf + OFF_SC;        // exp(score), then wg
    float*  s_w  = smf + OFF_W;
    float*  s_wp = smf + OFF_WP;
    float*  redA = smf + OFF_RA;
    float*  redB = smf + OFF_RB;
    float4* s_pf = (float4*)(smf + OFF_PF);
    float4* s_r  = (float4*)(smf + OFF_PF);   // overlays prefetch after use

    const int b   = blockIdx.x;
    const int tid = threadIdx.x;
    const int ml  = tid & 15;           // float4 lane within a row
    const int rg  = tid >> 4;           // row group 0..31

    const float* mb = mem + (size_t)b * Ndim * Mdim;

    // prefetch wprev row into smem (group #1)
    cp_async8(&s_wp[tid * 2], wprev + b * Ndim + tid * 2);
    CP_COMMIT();

    // ---- hoist per-b scalars & small vectors ----
    const float bet = beta[b];
    const float gv  = gg[b];
    const float gm  = gamma[b];
    const float sh0 = ss[b * 3 + 0], sh1 = ss[b * 3 + 1], sh2 = ss[b * 3 + 2];
    const float4 e4 = *(const float4*)(ee + b * Mdim + ml * 4);
    const float4 a4 = *(const float4*)(aa + b * Mdim + ml * 4);

    // ---- k (+eps) and its norm (reduced within each 16-lane group) ----
    float4 k4 = *(const float4*)(kk + b * Mdim + ml * 4);
    const float kx = k4.x + EPSV, ky = k4.y + EPSV;
    const float kz = k4.z + EPSV, kw = k4.w + EPSV;
    float kn = kx * kx + ky * ky + kz * kz + kw * kw;
#pragma unroll
    for (int o = 8; o > 0; o >>= 1) kn += __shfl_xor_sync(0xffffffffu, kn, o);
    const float knorm = fmaxf(sqrtf(kn), COS_EPS);

    // ---- Phase 1: scores. 4 groups x 8 front-batched LDG.128, butterfly
    //      reduce-scatter; grp 0 checkpointed to smem; stores exp(score) ----
#pragma unroll
    for (int grp = 0; grp < 4; grp++) {
        float4 m[8];
#pragma unroll
        for (int j = 0; j < 8; j++) {
            const int n = grp * 256 + j * 32 + rg;
            m[j] = *(const float4*)(mb + (size_t)n * Mdim + ml * 4);
        }
        if (grp == 0) {
#pragma unroll
            for (int j = 0; j < 8; j++)
                SAVE[(j * 32 + rg) * 16 + ml] = m[j];
        }
        float v[16];
#pragma unroll
        for (int j = 0; j < 8; j++) {
            float d = m[j].x * kx;
            d = fmaf(m[j].y, ky, d); d = fmaf(m[j].z, kz, d);
            d = fmaf(m[j].w, kw, d);
            float s = m[j].x * m[j].x;
            s = fmaf(m[j].y, m[j].y, s); s = fmaf(m[j].z, m[j].z, s);
            s = fmaf(m[j].w, m[j].w, s);
            v[j]     = d;
            v[8 + j] = s;
        }
        int cnt = 16;
#pragma unroll
        for (int o = 8; o >= 1; o >>= 1) {
            cnt >>= 1;
            const bool hi = (ml & o);
#pragma unroll
            for (int i = 0; i < cnt; i++) {
                const float send = hi ? v[i] : v[i + cnt];
                const float recv = __shfl_xor_sync(0xffffffffu, send, o);
                v[i] = (hi ? v[i + cnt] : v[i]) + recv;
            }
        }
        const float other = __shfl_xor_sync(0xffffffffu, v[0], 8);
        if (ml < 8) {
            const int n = grp * 256 + ml * 32 + rg;
            s_sc[n] = __expf(bet * (v[0] / (fmaxf(sqrtf(other), COS_EPS) * knorm)));
        }
    }

    // prefetch P3's first 2 slices (grp3 j0/j1) into smem (group #2)
#pragma unroll
    for (int j = 0; j < 2; j++) {
        const int n = 3 * 256 + j * 32 + rg;
        cp_async16(&s_pf[j * 512 + tid], mb + (size_t)n * Mdim + ml * 4);
    }
    CP_COMMIT();
    __syncthreads();

    // ---- Phase 2: softmax (exp precomputed) / interpolate / shift /
    //      sharpen. 2 n per thread; 1-barrier reductions. ----
    {
        const int n0 = tid, n1 = tid + 512;
        const float ex0 = s_sc[n0];
        const float ex1 = s_sc[n1];
        CP_WAIT(1);                          // wprev ready (pf still in flight)
        const float wp0 = s_wp[n0];
        const float wp1 = s_wp[n1];

        const float esum = blk_sum512_1b(ex0 + ex1, redA, tid);
        const float inv_esum = 1.f / esum;
        const float wg0 = fmaf(gv, ex0 * inv_esum - wp0, wp0);
        const float wg1 = fmaf(gv, ex1 * inv_esum - wp1, wp1);
        s_sc[n0] = wg0;                      // reuse s_sc as wg buffer
        s_sc[n1] = wg1;
        __syncthreads();

        const float wh0 = sh0 * s_sc[(n0 + Ndim - 1) & (Ndim - 1)]
                        + sh1 * wg0 + sh2 * s_sc[(n0 + 1) & (Ndim - 1)];
        const float wh1 = sh0 * s_sc[(n1 + Ndim - 1) & (Ndim - 1)]
                        + sh1 * wg1 + sh2 * s_sc[(n1 + 1) & (Ndim - 1)];
        const float w0 = __powf(wh0, gm);
        const float w1 = __powf(wh1, gm);
        const float wsum = blk_sum512_1b(w0 + w1, redB, tid);
        const float inv = 1.f / (wsum + EPSV);
        s_w[n0] = w0 * inv;
        s_w[n1] = w1 * inv;
    }
    __syncthreads();

    // ---- Phase 3: read vector + erase/add write.
    //      grps 3..1 from gmem (reverse order, L2-hot; grp3 j0/j1 from
    //      the cp.async bridge); grp 0 from the smem checkpoint ----
    float* ob = out + (size_t)b * (Ndim + 1) * Mdim;

    float rx = 0.f, ry = 0.f, rz = 0.f, rw = 0.f;
    CP_WAIT(0);                              // bridge slices landed
#pragma unroll
    for (int grp = 3; grp >= 1; grp--) {
        float4 m[8];
#pragma unroll
        for (int j = 0; j < 8; j++) {
            const int n = grp * 256 + j * 32 + rg;
            if (grp == 3 && j < 2)
                m[j] = s_pf[j * 512 + tid];
            else
                m[j] = __ldcs((const float4*)(mb + (size_t)n * Mdim + ml * 4));
        }
#pragma unroll
        for (int j = 0; j < 8; j++) {
            const int n = grp * 256 + j * 32 + rg;
            const float wv = s_w[n];
            float4 o4;
            o4.x = fmaf(m[j].x, fmaf(-wv, e4.x, 1.f), wv * a4.x);
            o4.y = fmaf(m[j].y, fmaf(-wv, e4.y, 1.f), wv * a4.y);
            o4.z = fmaf(m[j].z, fmaf(-wv, e4.z, 1.f), wv * a4.z);
            o4.w = fmaf(m[j].w, fmaf(-wv, e4.w, 1.f), wv * a4.w);
            __stcs((float4*)(ob + (size_t)(1 + n) * Mdim + ml * 4), o4);
            rx = fmaf(wv, m[j].x, rx);
            ry = fmaf(wv, m[j].y, ry);
            rz = fmaf(wv, m[j].z, rz);
            rw = fmaf(wv, m[j].w, rw);
        }
    }
    // grp 0 rows from the smem checkpoint
#pragma unroll
    for (int j = 0; j < 8; j++) {
        const int n = j * 32 + rg;
        float4 m4 = SAVE[(j * 32 + rg) * 16 + ml];
        const float wv = s_w[n];
        float4 o4;
        o4.x = fmaf(m4.x, fmaf(-wv, e4.x, 1.f), wv * a4.x);
        o4.y = fmaf(m4.y, fmaf(-wv, e4.y, 1.f), wv * a4.y);
        o4.z = fmaf(m4.z, fmaf(-wv, e4.z, 1.f), wv * a4.z);
        o4.w = fmaf(m4.w, fmaf(-wv, e4.w, 1.f), wv * a4.w);
        __stcs((float4*)(ob + (size_t)(1 + n) * Mdim + ml * 4), o4);
        rx = fmaf(wv, m4.x, rx);
        ry = fmaf(wv, m4.y, ry);
        rz = fmaf(wv, m4.z, rz);
        rw = fmaf(wv, m4.w, rw);
    }

    // reduce read accumulators (512 -> 16 lanes); s_r overlays the bridge
    __syncthreads();                    // bridge reads complete
    s_r[tid] = make_float4(rx, ry, rz, rw);
    __syncthreads();
#pragma unroll
    for (int s = 256; s >= 16; s >>= 1) {
        if (tid < s) {
            float4 x = s_r[tid], y = s_r[tid + s];
            x.x += y.x; x.y += y.y; x.z += y.z; x.w += y.w;
            s_r[tid] = x;
        }
        __syncthreads();
    }
    if (tid < 16) __stcs((float4*)(ob + tid * 4), s_r[tid]);   // read row
}

// ---------------------------------------------------------------------------
extern "C" void kernel_launch(void* const* d_in, const int* in_sizes, int n_in,
                              void* d_out, int out_size) {
    const float* mem   = (const float*)d_in[0];
    const float* kk    = (const float*)d_in[1];
    const float* beta  = (const float*)d_in[2];
    const float* gg    = (const float*)d_in[3];
    const float* ss    = (const float*)d_in[4];
    const float* gamma = (const float*)d_in[5];
    const float* wprev = (const float*)d_in[6];
    const float* ee    = (const float*)d_in[7];
    const float* aa    = (const float*)d_in[8];
    float* out = (float*)d_out;

    cudaFuncSetAttribute(fused_ntm,
                         cudaFuncAttributeMaxDynamicSharedMemorySize, SMEM_BYTES);
    fused_ntm<<<Bdim, 512, SMEM_BYTES>>>(mem, kk, beta, gg, ss, gamma,
                                         wprev, ee, aa, out);
}